// round 5
// baseline (speedup 1.0000x reference)
#include <cuda_runtime.h>
#include <math.h>

#define HIDDEN 1024
#define HEADS  8
#define HEAD   128
#define BATCH  512
#define TILES_PER_BLOCK 4

__device__ __forceinline__ float dot4(float4 a, float4 b) {
    return a.x*b.x + a.y*b.y + a.z*b.z + a.w*b.w;
}

// ---------------------------------------------------------------------------
// Fully fused mLSTM step + gates + GroupNorm, 4 (b,h) tiles per block.
// Cross-tile load pipelining: while finishing tile t (rows 8..15 compute +
// epilogue reductions), the 8 first cell rows of tile t+1 are already in
// flight in the same cv[] register ring -> the DRAM read stream never stops
// inside a block. Zero extra register cost vs the single-tile version.
// ---------------------------------------------------------------------------
__global__ __launch_bounds__(256) void mlstm_fused_kernel(
    const float* __restrict__ q, const float* __restrict__ k,
    const float* __restrict__ v, const float* __restrict__ cell,
    const float* __restrict__ norm, const float* __restrict__ maxs,
    const float* __restrict__ Wi, const float* __restrict__ bi,
    const float* __restrict__ Wf, const float* __restrict__ bf,
    const float* __restrict__ gamma, const float* __restrict__ beta,
    float* __restrict__ out, float* __restrict__ cell_out,
    float* __restrict__ norm_out, float* __restrict__ max_out)
{
    int tid  = threadIdx.x;
    int lane = tid & 31;
    int warp = tid >> 5;
    int bh0  = blockIdx.x * TILES_PER_BLOCK;

    __shared__ __align__(16) float q_s[HEAD];
    __shared__ __align__(16) float k_s[HEAD];
    __shared__ __align__(16) float v_s[HEAD];
    __shared__ float4 snum[256];
    __shared__ float pig[8], pfg[8], pq[4], pm[4], pv[4];

    const float rsqrtD = 0.08838834764831845f;  // 1/sqrt(128)

    // per-thread slot inside a tile: warp = row-group, lane = float4 column
    const float4* cp = (const float4*)(cell + (size_t)bh0 * HEAD * HEAD)
                       + warp * 32 + lane;
    float4* op = cell_out
               ? (float4*)(cell_out + (size_t)bh0 * HEAD * HEAD) + warp * 32 + lane
               : (float4*)0;

    // ---- prologue: prefetch first 8 cell rows of tile 0 --------------------
    float4 cv[8];
    #pragma unroll
    for (int i = 0; i < 8; ++i)
        cv[i] = __ldcs(cp + i * 256);

    #pragma unroll 1
    for (int t = 0; t < TILES_PER_BLOCK; ++t) {
        int bh = bh0 + t;
        int b  = bh >> 3;
        int h  = bh & 7;
        bool has_next = (t + 1 < TILES_PER_BLOCK);

        // ---- gate pre-activations: igp/fgp = qkv_row . W[h] + b[h] ---------
        const float4* qrow = (const float4*)(q + (size_t)b * HIDDEN);
        const float4* krow = (const float4*)(k + (size_t)b * HIDDEN);
        const float4* vrow = (const float4*)(v + (size_t)b * HIDDEN);
        const float4* Wi4  = (const float4*)Wi + (size_t)h * 768;
        const float4* Wf4  = (const float4*)Wf + (size_t)h * 768;

        float4 xq = qrow[tid];
        float4 xk = krow[tid];
        float4 xv = vrow[tid];

        float ai = dot4(xq, Wi4[tid]) + dot4(xk, Wi4[256 + tid]) + dot4(xv, Wi4[512 + tid]);
        float af = dot4(xq, Wf4[tid]) + dot4(xk, Wf4[256 + tid]) + dot4(xv, Wf4[512 + tid]);

        // warp h already holds the head slice in registers -> stash to smem
        if (warp == h) {
            ((float4*)q_s)[lane] = xq;
            float4 sk;
            sk.x = xk.x * rsqrtD; sk.y = xk.y * rsqrtD;
            sk.z = xk.z * rsqrtD; sk.w = xk.w * rsqrtD;
            ((float4*)k_s)[lane] = sk;
            ((float4*)v_s)[lane] = xv;
        }

        #pragma unroll
        for (int off = 16; off > 0; off >>= 1) {
            ai += __shfl_xor_sync(0xffffffffu, ai, off);
            af += __shfl_xor_sync(0xffffffffu, af, off);
        }
        if (lane == 0) { pig[warp] = ai; pfg[warp] = af; }
        __syncthreads();                                   // sync #1

        float igp = bi[h], fgp = bf[h];
        #pragma unroll
        for (int w = 0; w < 8; ++w) { igp += pig[w]; fgp += pfg[w]; }

        float log_f = fminf(fgp, 0.f) - log1pf(expf(-fabsf(fgp)));  // log sigmoid
        float m_old = maxs[bh];
        float m_new = fmaxf(igp, m_old + log_f);
        float i_g   = expf(igp - m_new);
        float f_g   = expf(log_f + m_old - m_new);

        if (tid == 0 && max_out) max_out[bh] = m_new;

        // ---- norm update + qn partials (reduction lands at sync #2) --------
        if (tid < HEAD) {
            float nn = fmaf(f_g, norm[(size_t)bh * HEAD + tid], i_g * k_s[tid]);
            if (norm_out) norm_out[(size_t)bh * HEAD + tid] = nn;
            float qn = q_s[tid] * nn;
            #pragma unroll
            for (int off = 16; off > 0; off >>= 1)
                qn += __shfl_xor_sync(0xffffffffu, qn, off);
            if (lane == 0) pq[warp] = qn;
        }

        // ---- main stream: rolling depth-8 pipeline; i>=8 prefetches the ----
        // ---- NEXT tile's rows 0..7 so the stream spans the epilogue --------
        float4 vreg = ((const float4*)v_s)[lane];
        float4 num  = make_float4(0.f, 0.f, 0.f, 0.f);

        #pragma unroll
        for (int i = 0; i < 16; ++i) {
            float4 c = cv[i & 7];
            if (i < 8)
                cv[i & 7] = __ldcs(cp + (i + 8) * 256);
            else if (has_next)
                cv[i & 7] = __ldcs(cp + 4096 + (i - 8) * 256);  // next tile
            int r = i * 8 + warp;
            float a = i_g * k_s[r];
            float4 cn;
            cn.x = fmaf(f_g, c.x, a * vreg.x);
            cn.y = fmaf(f_g, c.y, a * vreg.y);
            cn.z = fmaf(f_g, c.z, a * vreg.z);
            cn.w = fmaf(f_g, c.w, a * vreg.w);
            if (op) __stcs(op + i * 256, cn);
            float qr = q_s[r];
            num.x = fmaf(qr, cn.x, num.x);
            num.y = fmaf(qr, cn.y, num.y);
            num.z = fmaf(qr, cn.z, num.z);
            num.w = fmaf(qr, cn.w, num.w);
        }

        // ---- numerator reduction over the 8 row-groups ----------------------
        snum[tid] = num;
        __syncthreads();                                   // sync #2 (covers pq)
        if (tid < 32) {
            float4 a = snum[tid];
            #pragma unroll
            for (int j = 1; j < 8; ++j) {
                float4 bb = snum[tid + 32 * j];
                a.x += bb.x; a.y += bb.y; a.z += bb.z; a.w += bb.w;
            }
            snum[tid] = a;   // flattened: num[0..127]
        }
        __syncthreads();                                   // sync #3

        // ---- denominator + out_pre + GN stats -------------------------------
        float o = 0.f, so = 0.f, so2 = 0.f;
        if (tid < HEAD) {
            float qn    = pq[0] + pq[1] + pq[2] + pq[3];
            float denom = fmaxf(fabsf(qn), expf(-m_new)) + 1e-6f;
            o   = ((const float*)snum)[tid] / denom;
            so  = o;
            so2 = o * o;
        }
        #pragma unroll
        for (int off = 16; off > 0; off >>= 1) {
            so  += __shfl_xor_sync(0xffffffffu, so,  off);
            so2 += __shfl_xor_sync(0xffffffffu, so2, off);
        }
        if (tid < HEAD && lane == 0) { pm[warp] = so; pv[warp] = so2; }
        __syncthreads();                                   // sync #4

        if (tid < HEAD) {
            float mu   = (pm[0] + pm[1] + pm[2] + pm[3]) * (1.f / HEAD);
            float var  = (pv[0] + pv[1] + pv[2] + pv[3]) * (1.f / HEAD) - mu * mu;
            float rstd = rsqrtf(var + 1e-5f);
            int ch = h * HEAD + tid;
            out[(size_t)b * HIDDEN + ch] = (o - mu) * rstd * gamma[ch] + beta[ch];
        }

        cp += 4096;                       // advance one tile (128*128/4 float4)
        if (op) op += 4096;
    }
}

// ---------------------------------------------------------------------------
extern "C" void kernel_launch(void* const* d_in, const int* in_sizes, int n_in,
                              void* d_out, int out_size)
{
    const float* q     = (const float*)d_in[0];
    const float* k     = (const float*)d_in[1];
    const float* v     = (const float*)d_in[2];
    const float* cell  = (const float*)d_in[3];
    const float* norm  = (const float*)d_in[4];
    const float* maxs  = (const float*)d_in[5];
    const float* Wi    = (const float*)d_in[6];
    const float* bi    = (const float*)d_in[7];
    const float* Wf    = (const float*)d_in[8];
    const float* bf    = (const float*)d_in[9];
    const float* gamma = (const float*)d_in[10];
    const float* beta  = (const float*)d_in[11];

    float* out = (float*)d_out;

    const size_t OUT_N  = (size_t)BATCH * HIDDEN;                 // 524288
    const size_t CELL_N = (size_t)BATCH * HEADS * HEAD * HEAD;    // 67108864
    const size_t NORM_N = (size_t)BATCH * HEADS * HEAD;           // 524288
    const size_t MAX_N  = (size_t)BATCH * HEADS;                  // 4096

    float* cell_out = 0;
    float* norm_out = 0;
    float* max_out  = 0;
    if ((size_t)out_size >= OUT_N + CELL_N + NORM_N + MAX_N) {
        cell_out = out + OUT_N;
        norm_out = cell_out + CELL_N;
        max_out  = norm_out + NORM_N;
    }

    mlstm_fused_kernel<<<(BATCH * HEADS) / TILES_PER_BLOCK, 256>>>(
        q, k, v, cell, norm, maxs, Wi, bi, Wf, bf, gamma, beta,
        out, cell_out, norm_out, max_out);
}

// round 6
// speedup vs baseline: 1.2233x; 1.2233x over previous
#include <cuda_runtime.h>
#include <math.h>

#define HIDDEN 1024
#define HEADS  8
#define HEAD   128
#define BATCH  512

__device__ __forceinline__ float dot4(float4 a, float4 b) {
    return a.x*b.x + a.y*b.y + a.z*b.z + a.w*b.w;
}

// ---------------------------------------------------------------------------
// Single fully fused kernel: gate GEMV + mLSTM step + GroupNorm.
// One block per (b,h), 256 threads, ONE tile per block (round-4 structure:
// the multi-tile variant regressed by dropping CTAs/SM).
// Depth-4 rolling load ring (16 regs) + launch_bounds(256,5) -> <=51 regs
// -> 5 CTAs/SM, 40 warps: latency hidden by warp count, aggregate MLP
// (5*8*4 LDG.128 per SM = 80KB in flight) still far above the ~15KB needed.
// ---------------------------------------------------------------------------
__global__ __launch_bounds__(256, 5) void mlstm_fused_kernel(
    const float* __restrict__ q, const float* __restrict__ k,
    const float* __restrict__ v, const float* __restrict__ cell,
    const float* __restrict__ norm, const float* __restrict__ maxs,
    const float* __restrict__ Wi, const float* __restrict__ bi,
    const float* __restrict__ Wf, const float* __restrict__ bf,
    const float* __restrict__ gamma, const float* __restrict__ beta,
    float* __restrict__ out, float* __restrict__ cell_out,
    float* __restrict__ norm_out, float* __restrict__ max_out)
{
    int bh   = blockIdx.x;
    int b    = bh >> 3;
    int h    = bh & 7;
    int tid  = threadIdx.x;
    int lane = tid & 31;
    int warp = tid >> 5;

    __shared__ __align__(16) float q_s[HEAD];
    __shared__ __align__(16) float k_s[HEAD];
    __shared__ __align__(16) float v_s[HEAD];
    __shared__ float4 snum[256];
    __shared__ float pig[8], pfg[8], pq[4], pm[4], pv[4];

    const float rsqrtD = 0.08838834764831845f;  // 1/sqrt(128)

    // ---- cell tile pointers: warp = row-group, lane = float4 column --------
    const float4* cp = (const float4*)(cell + (size_t)bh * HEAD * HEAD)
                       + warp * 32 + lane;
    float4* op = cell_out
               ? (float4*)(cell_out + (size_t)bh * HEAD * HEAD) + warp * 32 + lane
               : (float4*)0;

    // ---- prefetch first 4 cell rows BEFORE the gate GEMV -------------------
    float4 cv[4];
    #pragma unroll
    for (int i = 0; i < 4; ++i)
        cv[i] = __ldcs(cp + i * 256);

    // ---- gate pre-activations: igp/fgp = qkv_row . W[h] + b[h] -------------
    const float4* qrow = (const float4*)(q + (size_t)b * HIDDEN);
    const float4* krow = (const float4*)(k + (size_t)b * HIDDEN);
    const float4* vrow = (const float4*)(v + (size_t)b * HIDDEN);
    const float4* Wi4  = (const float4*)Wi + (size_t)h * 768;
    const float4* Wf4  = (const float4*)Wf + (size_t)h * 768;

    float4 xq = qrow[tid];
    float4 xk = krow[tid];
    float4 xv = vrow[tid];

    float ai = dot4(xq, Wi4[tid]) + dot4(xk, Wi4[256 + tid]) + dot4(xv, Wi4[512 + tid]);
    float af = dot4(xq, Wf4[tid]) + dot4(xk, Wf4[256 + tid]) + dot4(xv, Wf4[512 + tid]);

    // warp h already holds the head slice in registers -> stash to smem
    if (warp == h) {
        ((float4*)q_s)[lane] = xq;
        float4 sk;
        sk.x = xk.x * rsqrtD; sk.y = xk.y * rsqrtD;
        sk.z = xk.z * rsqrtD; sk.w = xk.w * rsqrtD;
        ((float4*)k_s)[lane] = sk;
        ((float4*)v_s)[lane] = xv;
    }

    #pragma unroll
    for (int off = 16; off > 0; off >>= 1) {
        ai += __shfl_xor_sync(0xffffffffu, ai, off);
        af += __shfl_xor_sync(0xffffffffu, af, off);
    }
    if (lane == 0) { pig[warp] = ai; pfg[warp] = af; }
    __syncthreads();                                   // sync #1

    float igp = bi[h], fgp = bf[h];
    #pragma unroll
    for (int w = 0; w < 8; ++w) { igp += pig[w]; fgp += pfg[w]; }

    float log_f = fminf(fgp, 0.f) - log1pf(expf(-fabsf(fgp)));   // log sigmoid
    float m_old = maxs[bh];
    float m_new = fmaxf(igp, m_old + log_f);
    float i_g   = expf(igp - m_new);
    float f_g   = expf(log_f + m_old - m_new);

    if (tid == 0 && max_out) max_out[bh] = m_new;

    // ---- norm update + qn partials (reduction deferred to sync #2) ---------
    if (tid < HEAD) {
        float nn = fmaf(f_g, norm[(size_t)bh * HEAD + tid], i_g * k_s[tid]);
        if (norm_out) norm_out[(size_t)bh * HEAD + tid] = nn;
        float qn = q_s[tid] * nn;
        #pragma unroll
        for (int off = 16; off > 0; off >>= 1)
            qn += __shfl_xor_sync(0xffffffffu, qn, off);
        if (lane == 0) pq[warp] = qn;
    }

    // ---- main stream: rolling depth-4 pipeline over 16 rows -----------------
    float4 vreg = ((const float4*)v_s)[lane];
    float4 num  = make_float4(0.f, 0.f, 0.f, 0.f);

    #pragma unroll
    for (int i = 0; i < 16; ++i) {
        float4 c = cv[i & 3];
        if (i + 4 < 16)
            cv[i & 3] = __ldcs(cp + (i + 4) * 256);   // keep 4 rows in flight
        int r = i * 8 + warp;
        float a = i_g * k_s[r];
        float4 cn;
        cn.x = fmaf(f_g, c.x, a * vreg.x);
        cn.y = fmaf(f_g, c.y, a * vreg.y);
        cn.z = fmaf(f_g, c.z, a * vreg.z);
        cn.w = fmaf(f_g, c.w, a * vreg.w);
        if (op) __stcs(op + i * 256, cn);
        float qr = q_s[r];
        num.x = fmaf(qr, cn.x, num.x);
        num.y = fmaf(qr, cn.y, num.y);
        num.z = fmaf(qr, cn.z, num.z);
        num.w = fmaf(qr, cn.w, num.w);
    }

    // ---- numerator reduction over the 8 row-groups --------------------------
    snum[tid] = num;
    __syncthreads();                                   // sync #2 (covers pq)
    if (tid < 32) {
        float4 a = snum[tid];
        #pragma unroll
        for (int j = 1; j < 8; ++j) {
            float4 bb = snum[tid + 32 * j];
            a.x += bb.x; a.y += bb.y; a.z += bb.z; a.w += bb.w;
        }
        snum[tid] = a;   // flattened: num[0..127]
    }
    __syncthreads();                                   // sync #3

    // ---- denominator + out_pre + GN stats -----------------------------------
    float o = 0.f, so = 0.f, so2 = 0.f;
    if (tid < HEAD) {
        float qn    = pq[0] + pq[1] + pq[2] + pq[3];
        float denom = fmaxf(fabsf(qn), expf(-m_new)) + 1e-6f;
        o   = ((const float*)snum)[tid] / denom;
        so  = o;
        so2 = o * o;
    }
    #pragma unroll
    for (int off = 16; off > 0; off >>= 1) {
        so  += __shfl_xor_sync(0xffffffffu, so,  off);
        so2 += __shfl_xor_sync(0xffffffffu, so2, off);
    }
    if (tid < HEAD && lane == 0) { pm[warp] = so; pv[warp] = so2; }
    __syncthreads();                                   // sync #4

    if (tid < HEAD) {
        float mu   = (pm[0] + pm[1] + pm[2] + pm[3]) * (1.f / HEAD);
        float var  = (pv[0] + pv[1] + pv[2] + pv[3]) * (1.f / HEAD) - mu * mu;
        float rstd = rsqrtf(var + 1e-5f);
        int ch = h * HEAD + tid;
        out[(size_t)b * HIDDEN + ch] = (o - mu) * rstd * gamma[ch] + beta[ch];
    }
}

// ---------------------------------------------------------------------------
extern "C" void kernel_launch(void* const* d_in, const int* in_sizes, int n_in,
                              void* d_out, int out_size)
{
    const float* q     = (const float*)d_in[0];
    const float* k     = (const float*)d_in[1];
    const float* v     = (const float*)d_in[2];
    const float* cell  = (const float*)d_in[3];
    const float* norm  = (const float*)d_in[4];
    const float* maxs  = (const float*)d_in[5];
    const float* Wi    = (const float*)d_in[6];
    const float* bi    = (const float*)d_in[7];
    const float* Wf    = (const float*)d_in[8];
    const float* bf    = (const float*)d_in[9];
    const float* gamma = (const float*)d_in[10];
    const float* beta  = (const float*)d_in[11];

    float* out = (float*)d_out;

    const size_t OUT_N  = (size_t)BATCH * HIDDEN;                 // 524288
    const size_t CELL_N = (size_t)BATCH * HEADS * HEAD * HEAD;    // 67108864
    const size_t NORM_N = (size_t)BATCH * HEADS * HEAD;           // 524288
    const size_t MAX_N  = (size_t)BATCH * HEADS;                  // 4096

    float* cell_out = 0;
    float* norm_out = 0;
    float* max_out  = 0;
    if ((size_t)out_size >= OUT_N + CELL_N + NORM_N + MAX_N) {
        cell_out = out + OUT_N;
        norm_out = cell_out + CELL_N;
        max_out  = norm_out + NORM_N;
    }

    mlstm_fused_kernel<<<BATCH * HEADS, 256>>>(q, k, v, cell, norm, maxs,
                                               Wi, bi, Wf, bf, gamma, beta,
                                               out, cell_out, norm_out, max_out);
}

// round 7
// speedup vs baseline: 1.2260x; 1.0022x over previous
#include <cuda_runtime.h>
#include <math.h>

#define HIDDEN 1024
#define HEADS  8
#define HEAD   128
#define BATCH  512

__device__ __forceinline__ float dot4(float4 a, float4 b) {
    return a.x*b.x + a.y*b.y + a.z*b.z + a.w*b.w;
}

// 256-bit global load/store (sm_100+), streaming (evict-first) policy.
__device__ __forceinline__ void ldg8_cs(const float* p, float4& a, float4& b) {
    asm volatile("ld.global.cs.v8.f32 {%0,%1,%2,%3,%4,%5,%6,%7}, [%8];"
        : "=f"(a.x), "=f"(a.y), "=f"(a.z), "=f"(a.w),
          "=f"(b.x), "=f"(b.y), "=f"(b.z), "=f"(b.w)
        : "l"(p));
}
__device__ __forceinline__ void stg8_cs(float* p, float4 a, float4 b) {
    asm volatile("st.global.cs.v8.f32 [%0], {%1,%2,%3,%4,%5,%6,%7,%8};"
        :: "l"(p),
           "f"(a.x), "f"(a.y), "f"(a.z), "f"(a.w),
           "f"(b.x), "f"(b.y), "f"(b.z), "f"(b.w)
        : "memory");
}

// ---------------------------------------------------------------------------
// Fully fused gate GEMV + mLSTM step + GroupNorm. One (b,h) tile per block,
// 256 threads, 4 CTAs/SM (round-4 structure — best measured).
// Cell tile streamed with 256-bit ld/st: thread owns 8 consecutive floats
// (lane&15 = column octet, row = 2*warp + (lane>>4)); 16 rows/iter, 8 iters.
// Depth-3 rolling ring (24 regs) issued at kernel entry so the gate GEMV
// hides under the first cell loads.
// ---------------------------------------------------------------------------
__global__ __launch_bounds__(256, 4) void mlstm_fused_kernel(
    const float* __restrict__ q, const float* __restrict__ k,
    const float* __restrict__ v, const float* __restrict__ cell,
    const float* __restrict__ norm, const float* __restrict__ maxs,
    const float* __restrict__ Wi, const float* __restrict__ bi,
    const float* __restrict__ Wf, const float* __restrict__ bf,
    const float* __restrict__ gamma, const float* __restrict__ beta,
    float* __restrict__ out, float* __restrict__ cell_out,
    float* __restrict__ norm_out, float* __restrict__ max_out)
{
    int bh   = blockIdx.x;
    int b    = bh >> 3;
    int h    = bh & 7;
    int tid  = threadIdx.x;
    int lane = tid & 31;
    int warp = tid >> 5;

    __shared__ __align__(16) float q_s[HEAD];
    __shared__ __align__(16) float k_s[HEAD];
    __shared__ __align__(16) float v_s[HEAD];
    __shared__ __align__(16) float4 snum8[256][2];   // per-thread float8 partials
    __shared__ float pig[8], pfg[8], pq[4], pm[4], pv[4];

    const float rsqrtD = 0.08838834764831845f;  // 1/sqrt(128)

    // ---- cell addressing: row0 = 2*warp + (lane>>4), col octet = lane&15 ---
    int rsub = (warp << 1) + (lane >> 4);        // 0..15 within each 16-row band
    int c8   = lane & 15;                        // column octet (8 floats)
    const float* cbase = cell + (size_t)bh * HEAD * HEAD + rsub * HEAD + c8 * 8;
    float* obase = cell_out
                 ? cell_out + (size_t)bh * HEAD * HEAD + rsub * HEAD + c8 * 8
                 : (float*)0;

    // ---- prefetch first 3 iterations' rows BEFORE the gate GEMV ------------
    float4 cva[3], cvb[3];
    #pragma unroll
    for (int i = 0; i < 3; ++i)
        ldg8_cs(cbase + i * 16 * HEAD, cva[i], cvb[i]);

    // ---- gate pre-activations: igp/fgp = qkv_row . W[h] + b[h] -------------
    const float4* qrow = (const float4*)(q + (size_t)b * HIDDEN);
    const float4* krow = (const float4*)(k + (size_t)b * HIDDEN);
    const float4* vrow = (const float4*)(v + (size_t)b * HIDDEN);
    const float4* Wi4  = (const float4*)Wi + (size_t)h * 768;
    const float4* Wf4  = (const float4*)Wf + (size_t)h * 768;

    float4 xq = qrow[tid];
    float4 xk = krow[tid];
    float4 xv = vrow[tid];

    float ai = dot4(xq, Wi4[tid]) + dot4(xk, Wi4[256 + tid]) + dot4(xv, Wi4[512 + tid]);
    float af = dot4(xq, Wf4[tid]) + dot4(xk, Wf4[256 + tid]) + dot4(xv, Wf4[512 + tid]);

    // warp h already holds the head slice in registers -> stash to smem
    if (warp == h) {
        ((float4*)q_s)[lane] = xq;
        float4 sk;
        sk.x = xk.x * rsqrtD; sk.y = xk.y * rsqrtD;
        sk.z = xk.z * rsqrtD; sk.w = xk.w * rsqrtD;
        ((float4*)k_s)[lane] = sk;
        ((float4*)v_s)[lane] = xv;
    }

    #pragma unroll
    for (int off = 16; off > 0; off >>= 1) {
        ai += __shfl_xor_sync(0xffffffffu, ai, off);
        af += __shfl_xor_sync(0xffffffffu, af, off);
    }
    if (lane == 0) { pig[warp] = ai; pfg[warp] = af; }
    __syncthreads();                                   // sync #1

    float igp = bi[h], fgp = bf[h];
    #pragma unroll
    for (int w = 0; w < 8; ++w) { igp += pig[w]; fgp += pfg[w]; }

    float log_f = fminf(fgp, 0.f) - log1pf(expf(-fabsf(fgp)));   // log sigmoid
    float m_old = maxs[bh];
    float m_new = fmaxf(igp, m_old + log_f);
    float i_g   = expf(igp - m_new);
    float f_g   = expf(log_f + m_old - m_new);

    if (tid == 0 && max_out) max_out[bh] = m_new;

    // ---- norm update + qn partials (reduction deferred to sync #2) ---------
    if (tid < HEAD) {
        float nn = fmaf(f_g, norm[(size_t)bh * HEAD + tid], i_g * k_s[tid]);
        if (norm_out) norm_out[(size_t)bh * HEAD + tid] = nn;
        float qn = q_s[tid] * nn;
        #pragma unroll
        for (int off = 16; off > 0; off >>= 1)
            qn += __shfl_xor_sync(0xffffffffu, qn, off);
        if (lane == 0) pq[warp] = qn;
    }

    // ---- main stream: 8 iterations of 16 rows, depth-3 rolling ring ---------
    float4 vlo = ((const float4*)v_s)[c8 * 2];
    float4 vhi = ((const float4*)v_s)[c8 * 2 + 1];
    float4 numa = make_float4(0.f, 0.f, 0.f, 0.f);
    float4 numb = make_float4(0.f, 0.f, 0.f, 0.f);

    #pragma unroll
    for (int i = 0; i < 8; ++i) {
        float4 ca = cva[i % 3], cb = cvb[i % 3];
        if (i + 3 < 8)
            ldg8_cs(cbase + (i + 3) * 16 * HEAD, cva[i % 3], cvb[i % 3]);
        int r = i * 16 + rsub;
        float a = i_g * k_s[r];
        float4 cna, cnb;
        cna.x = fmaf(f_g, ca.x, a * vlo.x);
        cna.y = fmaf(f_g, ca.y, a * vlo.y);
        cna.z = fmaf(f_g, ca.z, a * vlo.z);
        cna.w = fmaf(f_g, ca.w, a * vlo.w);
        cnb.x = fmaf(f_g, cb.x, a * vhi.x);
        cnb.y = fmaf(f_g, cb.y, a * vhi.y);
        cnb.z = fmaf(f_g, cb.z, a * vhi.z);
        cnb.w = fmaf(f_g, cb.w, a * vhi.w);
        if (obase) stg8_cs(obase + i * 16 * HEAD, cna, cnb);
        float qr = q_s[r];
        numa.x = fmaf(qr, cna.x, numa.x);
        numa.y = fmaf(qr, cna.y, numa.y);
        numa.z = fmaf(qr, cna.z, numa.z);
        numa.w = fmaf(qr, cna.w, numa.w);
        numb.x = fmaf(qr, cnb.x, numb.x);
        numb.y = fmaf(qr, cnb.y, numb.y);
        numb.z = fmaf(qr, cnb.z, numb.z);
        numb.w = fmaf(qr, cnb.w, numb.w);
    }

    // ---- numerator reduction: 16 contributor threads per column ------------
    snum8[tid][0] = numa;
    snum8[tid][1] = numb;
    __syncthreads();                                   // sync #2 (covers pq)

    // thread tid<128 owns output column tid: contributors are tids {g+16j},
    // g = tid>>3; element index e = tid&7 inside the float8.
    float numc = 0.f;
    if (tid < HEAD) {
        int g = tid >> 3;
        int e = tid & 7;
        #pragma unroll
        for (int j = 0; j < 16; ++j)
            numc += ((const float*)&snum8[g + 16 * j][0])[e];
    }

    // ---- denominator + out_pre + GN stats -----------------------------------
    float o = 0.f, so = 0.f, so2 = 0.f;
    if (tid < HEAD) {
        float qn    = pq[0] + pq[1] + pq[2] + pq[3];
        float denom = fmaxf(fabsf(qn), expf(-m_new)) + 1e-6f;
        o   = numc / denom;
        so  = o;
        so2 = o * o;
    }
    #pragma unroll
    for (int off = 16; off > 0; off >>= 1) {
        so  += __shfl_xor_sync(0xffffffffu, so,  off);
        so2 += __shfl_xor_sync(0xffffffffu, so2, off);
    }
    if (tid < HEAD && lane == 0) { pm[warp] = so; pv[warp] = so2; }
    __syncthreads();                                   // sync #3

    if (tid < HEAD) {
        float mu   = (pm[0] + pm[1] + pm[2] + pm[3]) * (1.f / HEAD);
        float var  = (pv[0] + pv[1] + pv[2] + pv[3]) * (1.f / HEAD) - mu * mu;
        float rstd = rsqrtf(var + 1e-5f);
        int ch = h * HEAD + tid;
        out[(size_t)b * HIDDEN + ch] = (o - mu) * rstd * gamma[ch] + beta[ch];
    }
}

// ---------------------------------------------------------------------------
extern "C" void kernel_launch(void* const* d_in, const int* in_sizes, int n_in,
                              void* d_out, int out_size)
{
    const float* q     = (const float*)d_in[0];
    const float* k     = (const float*)d_in[1];
    const float* v     = (const float*)d_in[2];
    const float* cell  = (const float*)d_in[3];
    const float* norm  = (const float*)d_in[4];
    const float* maxs  = (const float*)d_in[5];
    const float* Wi    = (const float*)d_in[6];
    const float* bi    = (const float*)d_in[7];
    const float* Wf    = (const float*)d_in[8];
    const float* bf    = (const float*)d_in[9];
    const float* gamma = (const float*)d_in[10];
    const float* beta  = (const float*)d_in[11];

    float* out = (float*)d_out;

    const size_t OUT_N  = (size_t)BATCH * HIDDEN;                 // 524288
    const size_t CELL_N = (size_t)BATCH * HEADS * HEAD * HEAD;    // 67108864
    const size_t NORM_N = (size_t)BATCH * HEADS * HEAD;           // 524288
    const size_t MAX_N  = (size_t)BATCH * HEADS;                  // 4096

    float* cell_out = 0;
    float* norm_out = 0;
    float* max_out  = 0;
    if ((size_t)out_size >= OUT_N + CELL_N + NORM_N + MAX_N) {
        cell_out = out + OUT_N;
        norm_out = cell_out + CELL_N;
        max_out  = norm_out + NORM_N;
    }

    mlstm_fused_kernel<<<BATCH * HEADS, 256>>>(q, k, v, cell, norm, maxs,
                                               Wi, bi, Wf, bf, gamma, beta,
                                               out, cell_out, norm_out, max_out);
}

// round 8
// speedup vs baseline: 1.2297x; 1.0030x over previous
#include <cuda_runtime.h>
#include <math.h>

#define HIDDEN 1024
#define HEADS  8
#define HEAD   128
#define BATCH  512

__device__ __forceinline__ float dot4(float4 a, float4 b) {
    return a.x*b.x + a.y*b.y + a.z*b.z + a.w*b.w;
}

// 256-bit global load, streaming (evict-first) policy.
__device__ __forceinline__ void ldg8_cs(const float* p, float4& a, float4& b) {
    asm volatile("ld.global.cs.v8.f32 {%0,%1,%2,%3,%4,%5,%6,%7}, [%8];"
        : "=f"(a.x), "=f"(a.y), "=f"(a.z), "=f"(a.w),
          "=f"(b.x), "=f"(b.y), "=f"(b.z), "=f"(b.w)
        : "l"(p));
}
// 256-bit global store, DEFAULT write-back policy: let the 126MB L2 buffer
// dirty lines and emit long writeback bursts instead of fine-grained
// read/write interleave at DRAM (loads are .cs so they vacate L2 instantly).
__device__ __forceinline__ void stg8_wb(float* p, float4 a, float4 b) {
    asm volatile("st.global.v8.f32 [%0], {%1,%2,%3,%4,%5,%6,%7,%8};"
        :: "l"(p),
           "f"(a.x), "f"(a.y), "f"(a.z), "f"(a.w),
           "f"(b.x), "f"(b.y), "f"(b.z), "f"(b.w)
        : "memory");
}

// ---------------------------------------------------------------------------
// Fully fused gate GEMV + mLSTM step + GroupNorm. One (b,h) tile per block,
// 256 threads, 4 CTAs/SM. Cell tile streamed with 256-bit ld/st:
// thread owns 8 consecutive floats (lane&15 = column octet,
// row = 2*warp + (lane>>4)); 16 rows/iter, 8 iters, depth-3 rolling ring
// issued at kernel entry so the gate GEMV hides under the first cell loads.
// ---------------------------------------------------------------------------
__global__ __launch_bounds__(256, 4) void mlstm_fused_kernel(
    const float* __restrict__ q, const float* __restrict__ k,
    const float* __restrict__ v, const float* __restrict__ cell,
    const float* __restrict__ norm, const float* __restrict__ maxs,
    const float* __restrict__ Wi, const float* __restrict__ bi,
    const float* __restrict__ Wf, const float* __restrict__ bf,
    const float* __restrict__ gamma, const float* __restrict__ beta,
    float* __restrict__ out, float* __restrict__ cell_out,
    float* __restrict__ norm_out, float* __restrict__ max_out)
{
    int bh   = blockIdx.x;
    int b    = bh >> 3;
    int h    = bh & 7;
    int tid  = threadIdx.x;
    int lane = tid & 31;
    int warp = tid >> 5;

    __shared__ __align__(16) float q_s[HEAD];
    __shared__ __align__(16) float k_s[HEAD];
    __shared__ __align__(16) float v_s[HEAD];
    __shared__ __align__(16) float4 snum8[256][2];   // per-thread float8 partials
    __shared__ float pig[8], pfg[8], pq[4], pm[4], pv[4];

    const float rsqrtD = 0.08838834764831845f;  // 1/sqrt(128)

    // ---- cell addressing: row0 = 2*warp + (lane>>4), col octet = lane&15 ---
    int rsub = (warp << 1) + (lane >> 4);        // 0..15 within each 16-row band
    int c8   = lane & 15;                        // column octet (8 floats)
    const float* cbase = cell + (size_t)bh * HEAD * HEAD + rsub * HEAD + c8 * 8;
    float* obase = cell_out
                 ? cell_out + (size_t)bh * HEAD * HEAD + rsub * HEAD + c8 * 8
                 : (float*)0;

    // ---- prefetch first 3 iterations' rows BEFORE the gate GEMV ------------
    float4 cva[3], cvb[3];
    #pragma unroll
    for (int i = 0; i < 3; ++i)
        ldg8_cs(cbase + i * 16 * HEAD, cva[i], cvb[i]);

    // ---- gate pre-activations: igp/fgp = qkv_row . W[h] + b[h] -------------
    const float4* qrow = (const float4*)(q + (size_t)b * HIDDEN);
    const float4* krow = (const float4*)(k + (size_t)b * HIDDEN);
    const float4* vrow = (const float4*)(v + (size_t)b * HIDDEN);
    const float4* Wi4  = (const float4*)Wi + (size_t)h * 768;
    const float4* Wf4  = (const float4*)Wf + (size_t)h * 768;

    float4 xq = qrow[tid];
    float4 xk = krow[tid];
    float4 xv = vrow[tid];

    float ai = dot4(xq, Wi4[tid]) + dot4(xk, Wi4[256 + tid]) + dot4(xv, Wi4[512 + tid]);
    float af = dot4(xq, Wf4[tid]) + dot4(xk, Wf4[256 + tid]) + dot4(xv, Wf4[512 + tid]);

    // warp h already holds the head slice in registers -> stash to smem
    if (warp == h) {
        ((float4*)q_s)[lane] = xq;
        float4 sk;
        sk.x = xk.x * rsqrtD; sk.y = xk.y * rsqrtD;
        sk.z = xk.z * rsqrtD; sk.w = xk.w * rsqrtD;
        ((float4*)k_s)[lane] = sk;
        ((float4*)v_s)[lane] = xv;
    }

    #pragma unroll
    for (int off = 16; off > 0; off >>= 1) {
        ai += __shfl_xor_sync(0xffffffffu, ai, off);
        af += __shfl_xor_sync(0xffffffffu, af, off);
    }
    if (lane == 0) { pig[warp] = ai; pfg[warp] = af; }
    __syncthreads();                                   // sync #1

    float igp = bi[h], fgp = bf[h];
    #pragma unroll
    for (int w = 0; w < 8; ++w) { igp += pig[w]; fgp += pfg[w]; }

    float log_f = fminf(fgp, 0.f) - log1pf(expf(-fabsf(fgp)));   // log sigmoid
    float m_old = maxs[bh];
    float m_new = fmaxf(igp, m_old + log_f);
    float i_g   = expf(igp - m_new);
    float f_g   = expf(log_f + m_old - m_new);

    if (tid == 0 && max_out) max_out[bh] = m_new;

    // ---- norm update + qn partials (reduction deferred to sync #2) ---------
    if (tid < HEAD) {
        float nn = fmaf(f_g, norm[(size_t)bh * HEAD + tid], i_g * k_s[tid]);
        if (norm_out) norm_out[(size_t)bh * HEAD + tid] = nn;
        float qn = q_s[tid] * nn;
        #pragma unroll
        for (int off = 16; off > 0; off >>= 1)
            qn += __shfl_xor_sync(0xffffffffu, qn, off);
        if (lane == 0) pq[warp] = qn;
    }

    // ---- main stream: 8 iterations of 16 rows, depth-3 rolling ring ---------
    float4 vlo = ((const float4*)v_s)[c8 * 2];
    float4 vhi = ((const float4*)v_s)[c8 * 2 + 1];
    float4 numa = make_float4(0.f, 0.f, 0.f, 0.f);
    float4 numb = make_float4(0.f, 0.f, 0.f, 0.f);

    #pragma unroll
    for (int i = 0; i < 8; ++i) {
        float4 ca = cva[i % 3], cb = cvb[i % 3];
        if (i + 3 < 8)
            ldg8_cs(cbase + (i + 3) * 16 * HEAD, cva[i % 3], cvb[i % 3]);
        int r = i * 16 + rsub;
        float a = i_g * k_s[r];
        float4 cna, cnb;
        cna.x = fmaf(f_g, ca.x, a * vlo.x);
        cna.y = fmaf(f_g, ca.y, a * vlo.y);
        cna.z = fmaf(f_g, ca.z, a * vlo.z);
        cna.w = fmaf(f_g, ca.w, a * vlo.w);
        cnb.x = fmaf(f_g, cb.x, a * vhi.x);
        cnb.y = fmaf(f_g, cb.y, a * vhi.y);
        cnb.z = fmaf(f_g, cb.z, a * vhi.z);
        cnb.w = fmaf(f_g, cb.w, a * vhi.w);
        if (obase) stg8_wb(obase + i * 16 * HEAD, cna, cnb);
        float qr = q_s[r];
        numa.x = fmaf(qr, cna.x, numa.x);
        numa.y = fmaf(qr, cna.y, numa.y);
        numa.z = fmaf(qr, cna.z, numa.z);
        numa.w = fmaf(qr, cna.w, numa.w);
        numb.x = fmaf(qr, cnb.x, numb.x);
        numb.y = fmaf(qr, cnb.y, numb.y);
        numb.z = fmaf(qr, cnb.z, numb.z);
        numb.w = fmaf(qr, cnb.w, numb.w);
    }

    // ---- numerator reduction: 16 contributor threads per column ------------
    snum8[tid][0] = numa;
    snum8[tid][1] = numb;
    __syncthreads();                                   // sync #2 (covers pq)

    // thread tid<128 owns output column tid: contributors are tids {g+16j},
    // g = tid>>3; element index e = tid&7 inside the float8.
    float numc = 0.f;
    if (tid < HEAD) {
        int g = tid >> 3;
        int e = tid & 7;
        #pragma unroll
        for (int j = 0; j < 16; ++j)
            numc += ((const float*)&snum8[g + 16 * j][0])[e];
    }

    // ---- denominator + out_pre + GN stats -----------------------------------
    float o = 0.f, so = 0.f, so2 = 0.f;
    if (tid < HEAD) {
        float qn    = pq[0] + pq[1] + pq[2] + pq[3];
        float denom = fmaxf(fabsf(qn), expf(-m_new)) + 1e-6f;
        o   = numc / denom;
        so  = o;
        so2 = o * o;
    }
    #pragma unroll
    for (int off = 16; off > 0; off >>= 1) {
        so  += __shfl_xor_sync(0xffffffffu, so,  off);
        so2 += __shfl_xor_sync(0xffffffffu, so2, off);
    }
    if (tid < HEAD && lane == 0) { pm[warp] = so; pv[warp] = so2; }
    __syncthreads();                                   // sync #3

    if (tid < HEAD) {
        float mu   = (pm[0] + pm[1] + pm[2] + pm[3]) * (1.f / HEAD);
        float var  = (pv[0] + pv[1] + pv[2] + pv[3]) * (1.f / HEAD) - mu * mu;
        float rstd = rsqrtf(var + 1e-5f);
        int ch = h * HEAD + tid;
        out[(size_t)b * HIDDEN + ch] = (o - mu) * rstd * gamma[ch] + beta[ch];
    }
}

// ---------------------------------------------------------------------------
extern "C" void kernel_launch(void* const* d_in, const int* in_sizes, int n_in,
                              void* d_out, int out_size)
{
    const float* q     = (const float*)d_in[0];
    const float* k     = (const float*)d_in[1];
    const float* v     = (const float*)d_in[2];
    const float* cell  = (const float*)d_in[3];
    const float* norm  = (const float*)d_in[4];
    const float* maxs  = (const float*)d_in[5];
    const float* Wi    = (const float*)d_in[6];
    const float* bi    = (const float*)d_in[7];
    const float* Wf    = (const float*)d_in[8];
    const float* bf    = (const float*)d_in[9];
    const float* gamma = (const float*)d_in[10];
    const float* beta  = (const float*)d_in[11];

    float* out = (float*)d_out;

    const size_t OUT_N  = (size_t)BATCH * HIDDEN;                 // 524288
    const size_t CELL_N = (size_t)BATCH * HEADS * HEAD * HEAD;    // 67108864
    const size_t NORM_N = (size_t)BATCH * HEADS * HEAD;           // 524288
    const size_t MAX_N  = (size_t)BATCH * HEADS;                  // 4096

    float* cell_out = 0;
    float* norm_out = 0;
    float* max_out  = 0;
    if ((size_t)out_size >= OUT_N + CELL_N + NORM_N + MAX_N) {
        cell_out = out + OUT_N;
        norm_out = cell_out + CELL_N;
        max_out  = norm_out + NORM_N;
    }

    mlstm_fused_kernel<<<BATCH * HEADS, 256>>>(q, k, v, cell, norm, maxs,
                                               Wi, bi, Wf, bf, gamma, beta,
                                               out, cell_out, norm_out, max_out);
}